// round 14
// baseline (speedup 1.0000x reference)
#include <cuda_runtime.h>
#include <cuda_fp16.h>
#include <cstdint>

// Problem constants
#define Tn   2048
#define Bn   64
#define Vn   4096
#define En   128
#define H2n  128
#define Sn   8

// Scratch (no allocations allowed)
__device__ float g_proj[2][Vn * 512];      // proj[d][v][gate] = W_ih_d @ emb[v] + b_d (16 MB, L2-resident)
__device__ float g_pooled[Bn * Sn * 256];  // pooled[b][s][h]  (512 KB)

// ---------------------------------------------------------------------------
// helpers
// ---------------------------------------------------------------------------
__device__ __forceinline__ unsigned long long ffma2(unsigned long long a,
                                                    unsigned long long b,
                                                    unsigned long long c) {
    unsigned long long d;
    asm("fma.rn.f32x2 %0, %1, %2, %3;" : "=l"(d) : "l"(a), "l"(b), "l"(c));
    return d;
}
__device__ __forceinline__ float2 unpack2(unsigned long long u) {
    float2 f;
    f.x = __uint_as_float((unsigned)(u & 0xffffffffull));
    f.y = __uint_as_float((unsigned)(u >> 32));
    return f;
}
__device__ __forceinline__ float tanhf_fast(float x) {
    float y; asm("tanh.approx.f32 %0, %1;" : "=f"(y) : "f"(x)); return y;
}

// ---------------------------------------------------------------------------
// Kernel A: proj[d][v][r] = dot(emb[v], W_ih_d[r]) + b_d[r]
// grid (32, 4): y -> (dir, row-half). 256 threads; thread j owns row r = half*256+j,
// ALL 128 row weights in registers (64 f32x2). 128 v per block, 2 v per iter (ILP).
// ---------------------------------------------------------------------------
#define PROJ_VT 128
#define PROJ_SMEM (PROJ_VT * En * 4)   // 65536 B

__global__ void __launch_bounds__(256, 1)
proj_kernel(const float* __restrict__ emb,
            const float* __restrict__ Wf, const float* __restrict__ bf,
            const float* __restrict__ Wb, const float* __restrict__ bb) {
    extern __shared__ float xs[];   // [128 v][128 e]
    int vt   = blockIdx.x * PROJ_VT;
    int d    = blockIdx.y >> 1;
    int half = blockIdx.y & 1;
    int j    = threadIdx.x;
    int r    = half * 256 + j;

    const float* W    = d ? Wb : Wf;
    const float* bias = d ? bb : bf;
    float* outp = g_proj[d];

    // stage x tile: 128 v x 128 floats, coalesced float4
    {
        const float4* src = (const float4*)(emb + vt * En);
        float4* dst = (float4*)xs;
        for (int i = j; i < PROJ_VT * En / 4; i += 256) dst[i] = src[i];
    }

    // row weights fully in regs: 64 f32x2
    unsigned long long wr[64];
    {
        const ulonglong2* pw = (const ulonglong2*)(W + r * En);
#pragma unroll
        for (int q = 0; q < 32; q++) {
            ulonglong2 t = pw[q];
            wr[2 * q] = t.x; wr[2 * q + 1] = t.y;
        }
    }
    float bj = bias[r];
    __syncthreads();

    for (int v = 0; v < PROJ_VT; v += 2) {
        const ulonglong2* xv0 = (const ulonglong2*)(xs + v * En);
        const ulonglong2* xv1 = (const ulonglong2*)(xs + (v + 1) * En);
        unsigned long long a0 = 0, a1 = 0, a2 = 0, a3 = 0;
        unsigned long long b0 = 0, b1 = 0, b2 = 0, b3 = 0;
#pragma unroll
        for (int q = 0; q < 16; q++) {
            ulonglong2 hx0 = xv0[2 * q];
            ulonglong2 hx1 = xv0[2 * q + 1];
            ulonglong2 gx0 = xv1[2 * q];
            ulonglong2 gx1 = xv1[2 * q + 1];
            a0 = ffma2(wr[4 * q],     hx0.x, a0);
            a1 = ffma2(wr[4 * q + 1], hx0.y, a1);
            a2 = ffma2(wr[4 * q + 2], hx1.x, a2);
            a3 = ffma2(wr[4 * q + 3], hx1.y, a3);
            b0 = ffma2(wr[4 * q],     gx0.x, b0);
            b1 = ffma2(wr[4 * q + 1], gx0.y, b1);
            b2 = ffma2(wr[4 * q + 2], gx1.x, b2);
            b3 = ffma2(wr[4 * q + 3], gx1.y, b3);
        }
        float2 f0 = unpack2(a0), f1 = unpack2(a1);
        float2 f2 = unpack2(a2), f3 = unpack2(a3);
        outp[(vt + v) * 512 + r] =
            ((f0.x + f0.y) + (f1.x + f1.y)) + ((f2.x + f2.y) + (f3.x + f3.y)) + bj;
        float2 g0 = unpack2(b0), g1 = unpack2(b1);
        float2 g2 = unpack2(b2), g3 = unpack2(b3);
        outp[(vt + v + 1) * 512 + r] =
            ((g0.x + g0.y) + (g1.x + g1.y)) + ((g2.x + g2.y) + (g3.x + g3.y)) + bj;
    }
}

// ---------------------------------------------------------------------------
// Kernel B: recurrent biLSTM with fused ragged max-pool — fp16, one gate row
// per thread. grid 128 = (sample, direction); 512 threads.
// Thread k = 4m+q: computes the FULL 128-col dot of gate q (i,f,g,o) for
// h-index m. All 64 half2 weights in registers; h read as broadcast LDS
// (all lanes same address). No partial-sum combines: lane group {4m..4m+3}
// exchanges activations with 2 short shfls; lane 4m+3 owns c_m and h_m.
// Each lane runs a single activation type (branch-free, MUFU tanh).
// h stored packed half2, double-buffered. ONE barrier per step.
// ---------------------------------------------------------------------------
__global__ void __launch_bounds__(512, 1)
lstm_kernel(const int* __restrict__ sentence, const int* __restrict__ lens,
            const float* __restrict__ Whhf, const float* __restrict__ Whhb) {
    __shared__ uint4 h2b[2][16];          // 2 x 64 half2 (packed h, 256 B each)
    __shared__ float wmax[Sn * 128];      // [8][128]

    int bid = blockIdx.x;
    int b = bid >> 1, d = bid & 1;
    int L = lens[b];
    int w = (L + 7) >> 3;          // pooling window (>=128 for L in [1024,2048])
    int k = threadIdx.x;
    int m = k >> 2, q = k & 3;     // h-index, gate (0=i,1=f,2=g,3=o)
    int row = q * 128 + m;         // gate row in [0,512)

    const float* W     = d ? Whhb : Whhf;
    const float* projd = g_proj[d];
    const int*   toks  = sentence + b * Tn;

    // --- load W_hh row 'row' fully, quantize to 64 half2 regs ---
    __half2 w2[64];
    {
        const float4* pw = (const float4*)(W + row * En);
#pragma unroll
        for (int t = 0; t < 32; t++) {
            float4 v = pw[t];
            w2[2 * t]     = __floats2half2_rn(v.x, v.y);
            w2[2 * t + 1] = __floats2half2_rn(v.z, v.w);
        }
    }
    // zero both h buffers (32 uint4 total)
    if (k < 32) ((uint4*)h2b)[k] = make_uint4(0, 0, 0, 0);
    __syncthreads();

    float c = 0.f;
    float rmax = -3.402823e38f;
    int sdir = d ? -1 : 1;
    int seg  = d ? 7 : 0;                  // (L-1)/w == 7 for all valid L
    int cnt  = d ? (L - 7 * w) : w;        // steps until current segment closes
    int idx  = d ? (L - 1) : 0;            // current time index
    int rbuf = 0;
    bool isw = (k & 7) == 3;               // pack-writer threads (m even, q=3)

    // prefetch first xg value
    int tok0 = toks[idx];
    float xg = __ldg(projd + tok0 * 512 + row);

    for (int s = 0; s < L; s++) {
        // prefetch next step's xg (hides L2 latency under the FMA loop)
        int ni = idx + sdir;
        ni = ni < 0 ? 0 : (ni >= L ? L - 1 : ni);
        int tok2 = __ldg(toks + ni);
        float nx = __ldg(projd + tok2 * 512 + row);

        // --- full 128-col dot: 16 broadcast LDS.128, 64 HFMA2, 8 acc chains ---
        const uint4* hb = h2b[rbuf];
        __half2 acc[8];
#pragma unroll
        for (int a = 0; a < 8; a++) acc[a] = __float2half2_rn(0.f);
#pragma unroll
        for (int t = 0; t < 16; t++) {
            uint4 u = hb[t];                        // broadcast (uniform address)
            const __half2* hp = (const __half2*)&u; // 4 half2
#pragma unroll
            for (int i2 = 0; i2 < 4; i2++) {
                int n = t * 4 + i2;
                acc[n & 7] = __hfma2(w2[n], hp[i2], acc[n & 7]);
            }
        }
        __half2 t0 = __hadd2(__hadd2(acc[0], acc[1]), __hadd2(acc[2], acc[3]));
        __half2 t1 = __hadd2(__hadd2(acc[4], acc[5]), __hadd2(acc[6], acc[7]));
        __half2 tt = __hadd2(t0, t1);
        float gv = __low2float(tt) + __high2float(tt) + xg;

        // activation: lane q==2 -> tanh(gv); else sigmoid via 0.5*tanh(0.5x)+0.5
        float arg = (q == 2) ? gv : 0.5f * gv;
        float tv  = tanhf_fast(arg);
        float act = (q == 2) ? tv : fmaf(0.5f, tv, 0.5f);

        // lane-group exchange within {4m..4m+3}:
        //   xor 2: lane2 gets sig(i) [from lane0], lane3 gets sig(f) [from lane1]
        float a2 = __shfl_xor_sync(0xffffffffu, act, 2);
        float prod = act * a2;                      // lane2: tanh(g)*sig(i)
        //   xor 1: lane3 gets prod from lane2
        float pr = __shfl_xor_sync(0xffffffffu, prod, 1);

        // lane 4m+3 owns the cell state: a2 = sig(f), act = sig(o)
        c = a2 * c + pr;
        float hn = act * tanhf_fast(c);

        // pack (h_2t, h_2t+1) on threads k=8t+3 via xor 4, store half2
        float ho = __shfl_xor_sync(0xffffffffu, hn, 4);
        if (isw) ((__half2*)h2b[rbuf ^ 1])[k >> 3] = __floats2half2_rn(hn, ho);
        __syncthreads();
        if (q == 3) rmax = fmaxf(rmax, hn);

        // segment boundary: flush register max (7-8 crossings per chain)
        if (--cnt == 0) {
            if (q == 3) wmax[seg * 128 + m] = rmax;
            rmax = -3.402823e38f;
            seg += sdir;
            cnt = w;
        }
        idx = ni;
        xg = nx;
        rbuf ^= 1;                                  // swap double buffers
    }
    if (cnt != w && q == 3) wmax[seg * 128 + m] = rmax;   // pending partial segment
    __syncthreads();

    // epilogue: only window 7 can overlap the zero pad (pad length < 8 <= w)
    bool pad7 = (8 * w > L);
    for (int i = k; i < Sn * 128; i += 512) {
        int ss = i >> 7, kk = i & 127;
        float v = wmax[i];
        if (ss == 7 && pad7) v = fmaxf(v, 0.f);
        g_pooled[(b * Sn + ss) * 256 + d * 128 + kk] = v;
    }
}

// ---------------------------------------------------------------------------
// Kernel C: out[b][c] = b_dense[c] + sum_{s,h} pooled[b][s][h] * W_dense[c][h*8+s]
// ---------------------------------------------------------------------------
__global__ void dense_kernel(const float* __restrict__ Wd, const float* __restrict__ bd,
                             float* __restrict__ out) {
    int b = blockIdx.x, t = threadIdx.x;
    const float* p = g_pooled + b * 2048;
    float a0 = 0.f, a1 = 0.f;
    for (int i = t; i < 2048; i += 256) {
        int s = i >> 8, hh = i & 255;
        float v = p[i];
        a0 += v * Wd[hh * 8 + s];
        a1 += v * Wd[2048 + hh * 8 + s];
    }
#pragma unroll
    for (int o = 16; o > 0; o >>= 1) {
        a0 += __shfl_down_sync(0xffffffffu, a0, o);
        a1 += __shfl_down_sync(0xffffffffu, a1, o);
    }
    __shared__ float r0[8], r1[8];
    if ((t & 31) == 0) { r0[t >> 5] = a0; r1[t >> 5] = a1; }
    __syncthreads();
    if (t == 0) {
        float o0 = bd[0], o1 = bd[1];
#pragma unroll
        for (int i = 0; i < 8; i++) { o0 += r0[i]; o1 += r1[i]; }
        out[b * 2]     = o0;
        out[b * 2 + 1] = o1;
    }
}

// ---------------------------------------------------------------------------
// launch
// ---------------------------------------------------------------------------
extern "C" void kernel_launch(void* const* d_in, const int* in_sizes, int n_in,
                              void* d_out, int out_size) {
    const int*   sentence = (const int*)d_in[0];
    const int*   lens     = (const int*)d_in[1];
    const float* emb      = (const float*)d_in[2];
    const float* Wihf     = (const float*)d_in[3];
    const float* Whhf     = (const float*)d_in[4];
    const float* bf       = (const float*)d_in[5];
    const float* Wihb     = (const float*)d_in[6];
    const float* Whhb     = (const float*)d_in[7];
    const float* bb       = (const float*)d_in[8];
    const float* Wd       = (const float*)d_in[9];
    const float* bd       = (const float*)d_in[10];
    float* out = (float*)d_out;

    cudaFuncSetAttribute(proj_kernel, cudaFuncAttributeMaxDynamicSharedMemorySize, PROJ_SMEM);

    proj_kernel<<<dim3(Vn / PROJ_VT, 4), 256, PROJ_SMEM>>>(emb, Wihf, bf, Wihb, bb);
    lstm_kernel<<<128, 512>>>(sentence, lens, Whhf, Whhb);
    dense_kernel<<<Bn, 256>>>(Wd, bd, out);
}

// round 15
// speedup vs baseline: 1.1364x; 1.1364x over previous
#include <cuda_runtime.h>
#include <cuda_fp16.h>
#include <cstdint>

// Problem constants
#define Tn   2048
#define Bn   64
#define Vn   4096
#define En   128
#define H2n  128
#define Sn   8

// Scratch (no allocations allowed)
__device__ float g_proj[2][Vn * 512];      // proj[d][v][gate] = W_ih_d @ emb[v] + b_d (16 MB, L2-resident)
__device__ float g_pooled[Bn * Sn * 256];  // pooled[b][s][h]  (512 KB)

// ---------------------------------------------------------------------------
// helpers
// ---------------------------------------------------------------------------
__device__ __forceinline__ float tanhf_fast(float x) {
    float y; asm("tanh.approx.f32 %0, %1;" : "=f"(y) : "f"(x)); return y;
}
// sigmoid via MUFU tanh: sig(x) = 0.5*tanh(0.5x) + 0.5
__device__ __forceinline__ float sigm_fast(float x) {
    return fmaf(0.5f, tanhf_fast(0.5f * x), 0.5f);
}

// ---------------------------------------------------------------------------
// Kernel A: proj[d][v][r] = dot(emb[v], W_ih_d[r]) + b_d[r]   (fp16 dots)
// grid (32, 4): y -> (dir, row-half). 256 threads; thread j owns row r.
// x tile staged as half2 in smem (halves the LDS bytes vs fp32); row weights
// as 32 half2 regs. 128 v per block, 2 v per iter (ILP). Output fp32.
// ---------------------------------------------------------------------------
#define PROJ_VT 128
#define PROJ_SMEM (PROJ_VT * En * 2)   // 32768 B (half2 x tile)

__global__ void __launch_bounds__(256, 1)
proj_kernel(const float* __restrict__ emb,
            const float* __restrict__ Wf, const float* __restrict__ bf,
            const float* __restrict__ Wb, const float* __restrict__ bb) {
    extern __shared__ uint4 xsh[];   // [128 v][16 uint4]  (64 half2 per v)
    int vt   = blockIdx.x * PROJ_VT;
    int d    = blockIdx.y >> 1;
    int half = blockIdx.y & 1;
    int j    = threadIdx.x;
    int r    = half * 256 + j;

    const float* W    = d ? Wb : Wf;
    const float* bias = d ? bb : bf;
    float* outp = g_proj[d];

    // stage x tile as half2: each thread converts 16 float4 -> 8 uint4
    {
        const float4* src = (const float4*)(emb + vt * En);
        uint2* dst = (uint2*)xsh;
        for (int i = j; i < PROJ_VT * En / 4; i += 256) {
            float4 e = src[i];
            __half2 lo = __floats2half2_rn(e.x, e.y);
            __half2 hi = __floats2half2_rn(e.z, e.w);
            dst[i] = make_uint2(*(unsigned*)&lo, *(unsigned*)&hi);
        }
    }

    // row weights: 128 floats -> 64 half2 regs
    __half2 wh[64];
    {
        const float4* pw = (const float4*)(W + r * En);
#pragma unroll
        for (int q = 0; q < 32; q++) {
            float4 v = pw[q];
            wh[2 * q]     = __floats2half2_rn(v.x, v.y);
            wh[2 * q + 1] = __floats2half2_rn(v.z, v.w);
        }
    }
    float bj = bias[r];
    __syncthreads();

    for (int v = 0; v < PROJ_VT; v += 2) {
        const uint4* xv0 = xsh + v * 16;
        const uint4* xv1 = xsh + (v + 1) * 16;
        __half2 a[8], b[8];
#pragma unroll
        for (int t = 0; t < 16; t++) {
            uint4 u0 = xv0[t];                       // broadcast LDS.128
            uint4 u1 = xv1[t];
            const __half2* x0 = (const __half2*)&u0;
            const __half2* x1 = (const __half2*)&u1;
#pragma unroll
            for (int i2 = 0; i2 < 4; i2++) {
                int n = t * 4 + i2;
                if (n < 8) {
                    a[n] = __hmul2(wh[n], x0[i2]);
                    b[n] = __hmul2(wh[n], x1[i2]);
                } else {
                    a[n & 7] = __hfma2(wh[n], x0[i2], a[n & 7]);
                    b[n & 7] = __hfma2(wh[n], x1[i2], b[n & 7]);
                }
            }
        }
        __half2 sa = __hadd2(__hadd2(__hadd2(a[0], a[1]), __hadd2(a[2], a[3])),
                             __hadd2(__hadd2(a[4], a[5]), __hadd2(a[6], a[7])));
        __half2 sb = __hadd2(__hadd2(__hadd2(b[0], b[1]), __hadd2(b[2], b[3])),
                             __hadd2(__hadd2(b[4], b[5]), __hadd2(b[6], b[7])));
        outp[(vt + v) * 512 + r]     = __low2float(sa) + __high2float(sa) + bj;
        outp[(vt + v + 1) * 512 + r] = __low2float(sb) + __high2float(sb) + bj;
    }
}

// ---------------------------------------------------------------------------
// Kernel B: recurrent biLSTM with fused ragged max-pool — fp16 HFMA2 dots.
// grid 128 = (sample, direction); 256 threads (R12 structure — best measured).
// Pair (2j, 2j+1): thread p owns h-columns [64p, 64p+64) of gate rows
// i_j, f_j, g_j, o_j. All 4 gate halves in registers as half2 (128 regs),
// zero smem weight streaming. h packed half2, double-buffered.
// Changes vs R12: (a) tok prefetched 2 steps ahead / proj 1 step ahead so the
// dependent LDG chain is split across two steps; (b) accumulators initialized
// by __hmul2 (no 32 zero-MOVs per step).
// ---------------------------------------------------------------------------
__global__ void __launch_bounds__(256, 1)
lstm_kernel(const int* __restrict__ sentence, const int* __restrict__ lens,
            const float* __restrict__ Whhf, const float* __restrict__ Whhb) {
    __shared__ uint4 h2raw[2][18];        // 2 x 72 half2: [0..31], pad 4, [36..67]
    __shared__ float wmax[Sn * 128];      // [8][128]

    int bid = blockIdx.x;
    int b = bid >> 1, d = bid & 1;
    int L = lens[b];
    int w = (L + 7) >> 3;          // pooling window (>=128 for L in [1024,2048])
    int k = threadIdx.x;
    int j = k >> 1, p = k & 1;

    const float* W     = d ? Whhb : Whhf;
    const float* projd = g_proj[d];
    const int*   toks  = sentence + b * Tn;

    int rX = p ? (128 + j) : j;          // f : i   (xg row for gX)
    int rY = p ? (384 + j) : (256 + j);  // o : g   (xg row for gY)

    // --- load W_hh halves, quantize to half2 pairs (cols 2m, 2m+1) ---
    __half2 w2i[32], w2f[32], w2g[32], w2o[32];
    {
        int co = 64 * p;
        const float4* pi_ = (const float4*)(W + j * En + co);
        const float4* pf_ = (const float4*)(W + (128 + j) * En + co);
        const float4* pg_ = (const float4*)(W + (256 + j) * En + co);
        const float4* po_ = (const float4*)(W + (384 + j) * En + co);
#pragma unroll
        for (int q = 0; q < 16; q++) {
            float4 vi = pi_[q];
            w2i[2 * q]     = __floats2half2_rn(vi.x, vi.y);
            w2i[2 * q + 1] = __floats2half2_rn(vi.z, vi.w);
            float4 vf = pf_[q];
            w2f[2 * q]     = __floats2half2_rn(vf.x, vf.y);
            w2f[2 * q + 1] = __floats2half2_rn(vf.z, vf.w);
            float4 vg = pg_[q];
            w2g[2 * q]     = __floats2half2_rn(vg.x, vg.y);
            w2g[2 * q + 1] = __floats2half2_rn(vg.z, vg.w);
            float4 vo = po_[q];
            w2o[2 * q]     = __floats2half2_rn(vo.x, vo.y);
            w2o[2 * q + 1] = __floats2half2_rn(vo.z, vo.w);
        }
    }
    // zero both h buffers
    if (k < 36) {
        ((uint*)h2raw[0])[k * 2] = 0; ((uint*)h2raw[0])[k * 2 + 1] = 0;
        ((uint*)h2raw[1])[k * 2] = 0; ((uint*)h2raw[1])[k * 2 + 1] = 0;
    }
    __syncthreads();

    float c = 0.f;
    float rmax = -3.402823e38f;
    int sdir = d ? -1 : 1;
    int seg  = d ? 7 : 0;                  // (L-1)/w == 7 for all valid L
    int cnt  = d ? (L - 7 * w) : w;        // steps until current segment closes
    int idx  = d ? (L - 1) : 0;            // current time index
    // h2 writer: threads with (k&3)==1 own entry m = k>>2 (pairs h_2m, h_2m+1)
    int went  = (k >> 2) + (((k >> 2) >> 5) << 2);   // padded entry index
    bool isw  = (k & 3) == 1;

    int rbuf = 0;

    // deep prefetch: xg for step 0; token for step 1 already in flight
    int ni   = idx + sdir; ni = ni < 0 ? 0 : (ni >= L ? L - 1 : ni);
    int tok0 = toks[idx];
    int tokn = toks[ni];                       // token for t+1
    float xga = __ldg(projd + tok0 * 512 + rX);
    float xgb = __ldg(projd + tok0 * 512 + rY);

    for (int s = 0; s < L; s++) {
        // prefetch: tok(t+2) and proj[tok(t+1)] — each LDG gets a full step of cover
        int nni = ni + sdir; nni = nni < 0 ? 0 : (nni >= L ? L - 1 : nni);
        int toknn = __ldg(toks + nni);
        float nxa = __ldg(projd + tokn * 512 + rX);
        float nxb = __ldg(projd + tokn * 512 + rY);

        // --- load this thread's h half (32 half2) as 8 LDS.128 ---
        uint4 hu[8];
        {
            const uint4* hb = h2raw[rbuf] + p * 9;   // 36 half2 = 9 uint4 offset
#pragma unroll
            for (int i = 0; i < 8; i++) hu[i] = hb[i];
        }
        const __half2* hp = (const __half2*)hu;

        // --- 4 half-row dots, 8 half2 accumulator chains, init via mul ---
        __half2 ai[8], af[8], ag[8], ao[8];
#pragma unroll
        for (int m = 0; m < 8; m++) {
            __half2 h2 = hp[m];
            ai[m] = __hmul2(w2i[m], h2);
            af[m] = __hmul2(w2f[m], h2);
            ag[m] = __hmul2(w2g[m], h2);
            ao[m] = __hmul2(w2o[m], h2);
        }
#pragma unroll
        for (int m = 8; m < 32; m++) {
            int a = m & 7;
            __half2 h2 = hp[m];
            ai[a] = __hfma2(w2i[m], h2, ai[a]);
            af[a] = __hfma2(w2f[m], h2, af[a]);
            ag[a] = __hfma2(w2g[m], h2, ag[a]);
            ao[a] = __hfma2(w2o[m], h2, ao[a]);
        }
        // reduce: hadd2 tree then promote to fp32
        __half2 si = __hadd2(__hadd2(__hadd2(ai[0], ai[1]), __hadd2(ai[2], ai[3])),
                             __hadd2(__hadd2(ai[4], ai[5]), __hadd2(ai[6], ai[7])));
        __half2 sf = __hadd2(__hadd2(__hadd2(af[0], af[1]), __hadd2(af[2], af[3])),
                             __hadd2(__hadd2(af[4], af[5]), __hadd2(af[6], af[7])));
        __half2 sg = __hadd2(__hadd2(__hadd2(ag[0], ag[1]), __hadd2(ag[2], ag[3])),
                             __hadd2(__hadd2(ag[4], ag[5]), __hadd2(ag[6], ag[7])));
        __half2 so = __hadd2(__hadd2(__hadd2(ao[0], ao[1]), __hadd2(ao[2], ao[3])),
                             __hadd2(__hadd2(ao[4], ao[5]), __hadd2(ao[6], ao[7])));
        float pi = __low2float(si) + __high2float(si);
        float pf = __low2float(sf) + __high2float(sf);
        float pg = __low2float(sg) + __high2float(sg);
        float po = __low2float(so) + __high2float(so);

        // combine partials across the pair: even keeps i,g; odd keeps f,o
        float sendA = p ? pi : pf;
        float sendB = p ? pg : po;
        float recvA = __shfl_xor_sync(0xffffffffu, sendA, 1);
        float recvB = __shfl_xor_sync(0xffffffffu, sendB, 1);
        float gX = (p ? pf : pi) + recvA + xga;   // i (even) / f (odd)
        float gY = (p ? po : pg) + recvB + xgb;   // g (even) / o (odd)

        // activations on MUFU tanh
        float vX = sigm_fast(gX);                   // sig(i)/sig(f)
        float ty = tanhf_fast(p ? 0.5f * gY : gY);
        float vY = p ? fmaf(0.5f, ty, 0.5f) : ty;   // sig(o)/tanh(g)

        float pvr = __shfl_xor_sync(0xffffffffu, vX * vY, 1);  // sig(i)*tanh(g) -> odd

        c = vX * c + pvr;                           // meaningful on odd lanes
        float hn = vY * tanhf_fast(c);              // sig(o)*tanh(c)

        // pack h pair (h_2m, h_2m+1) from odd lanes 4m+1 / 4m+3, store half2
        float hpart = __shfl_xor_sync(0xffffffffu, hn, 2);
        if (isw) {
            ((__half2*)h2raw[rbuf ^ 1])[went] = __floats2half2_rn(hn, hpart);
        }
        __syncthreads();
        if (p) rmax = fmaxf(rmax, hn);

        // segment boundary: flush register max (7-8 crossings per chain)
        if (--cnt == 0) {
            if (p) wmax[seg * 128 + j] = rmax;
            rmax = -3.402823e38f;
            seg += sdir;
            cnt = w;
        }
        idx = ni; ni = nni; tokn = toknn;
        xga = nxa; xgb = nxb;
        rbuf ^= 1;                                  // swap double buffers
    }
    if (cnt != w && p) wmax[seg * 128 + j] = rmax;   // pending partial segment
    __syncthreads();

    // epilogue: only window 7 can overlap the zero pad (pad length < 8 <= w)
    bool pad7 = (8 * w > L);
    for (int i = k; i < Sn * 128; i += 256) {
        int s = i >> 7, kk = i & 127;
        float v = wmax[i];
        if (s == 7 && pad7) v = fmaxf(v, 0.f);
        g_pooled[(b * Sn + s) * 256 + d * 128 + kk] = v;
    }
}

// ---------------------------------------------------------------------------
// Kernel C: out[b][c] = b_dense[c] + sum_{s,h} pooled[b][s][h] * W_dense[c][h*8+s]
// ---------------------------------------------------------------------------
__global__ void dense_kernel(const float* __restrict__ Wd, const float* __restrict__ bd,
                             float* __restrict__ out) {
    int b = blockIdx.x, t = threadIdx.x;
    const float* p = g_pooled + b * 2048;
    float a0 = 0.f, a1 = 0.f;
    for (int i = t; i < 2048; i += 256) {
        int s = i >> 8, hh = i & 255;
        float v = p[i];
        a0 += v * Wd[hh * 8 + s];
        a1 += v * Wd[2048 + hh * 8 + s];
    }
#pragma unroll
    for (int o = 16; o > 0; o >>= 1) {
        a0 += __shfl_down_sync(0xffffffffu, a0, o);
        a1 += __shfl_down_sync(0xffffffffu, a1, o);
    }
    __shared__ float r0[8], r1[8];
    if ((t & 31) == 0) { r0[t >> 5] = a0; r1[t >> 5] = a1; }
    __syncthreads();
    if (t == 0) {
        float o0 = bd[0], o1 = bd[1];
#pragma unroll
        for (int i = 0; i < 8; i++) { o0 += r0[i]; o1 += r1[i]; }
        out[b * 2]     = o0;
        out[b * 2 + 1] = o1;
    }
}

// ---------------------------------------------------------------------------
// launch
// ---------------------------------------------------------------------------
extern "C" void kernel_launch(void* const* d_in, const int* in_sizes, int n_in,
                              void* d_out, int out_size) {
    const int*   sentence = (const int*)d_in[0];
    const int*   lens     = (const int*)d_in[1];
    const float* emb      = (const float*)d_in[2];
    const float* Wihf     = (const float*)d_in[3];
    const float* Whhf     = (const float*)d_in[4];
    const float* bf       = (const float*)d_in[5];
    const float* Wihb     = (const float*)d_in[6];
    const float* Whhb     = (const float*)d_in[7];
    const float* bb       = (const float*)d_in[8];
    const float* Wd       = (const float*)d_in[9];
    const float* bd       = (const float*)d_in[10];
    float* out = (float*)d_out;

    cudaFuncSetAttribute(proj_kernel, cudaFuncAttributeMaxDynamicSharedMemorySize, PROJ_SMEM);

    proj_kernel<<<dim3(Vn / PROJ_VT, 4), 256, PROJ_SMEM>>>(emb, Wihf, bf, Wihb, bb);
    lstm_kernel<<<128, 256>>>(sentence, lens, Whhf, Whhb);
    dense_kernel<<<Bn, 256>>>(Wd, bd, out);
}

// round 16
// speedup vs baseline: 1.2715x; 1.1189x over previous
#include <cuda_runtime.h>
#include <cuda_fp16.h>
#include <cstdint>

// Problem constants
#define Tn   2048
#define Bn   64
#define Vn   4096
#define En   128
#define H2n  128
#define Sn   8

// Scratch (no allocations allowed)
__device__ float g_proj[2][Vn * 512];      // proj[d][v][gate] = W_ih_d @ emb[v] + b_d (16 MB, L2-resident)
__device__ float g_pooled[Bn * Sn * 256];  // pooled[b][s][h]  (512 KB)

// ---------------------------------------------------------------------------
// helpers
// ---------------------------------------------------------------------------
__device__ __forceinline__ float tanhf_fast(float x) {
    float y; asm("tanh.approx.f32 %0, %1;" : "=f"(y) : "f"(x)); return y;
}
// sigmoid via MUFU tanh: sig(x) = 0.5*tanh(0.5x) + 0.5
__device__ __forceinline__ float sigm_fast(float x) {
    return fmaf(0.5f, tanhf_fast(0.5f * x), 0.5f);
}

// ---------------------------------------------------------------------------
// Kernel A: proj[d][v][r] = dot(emb[v], W_ih_d[r]) + b_d[r]   (fp16 dots)
// grid (32, 4): y -> (dir, row-half). 256 threads; thread j owns row r.
// x tile staged as half2 in smem; row weights as 64 half2 regs. 128 v per
// block, 2 v per iter (ILP). Output fp32.
// ---------------------------------------------------------------------------
#define PROJ_VT 128
#define PROJ_SMEM (PROJ_VT * En * 2)   // 32768 B (half2 x tile)

__global__ void __launch_bounds__(256, 1)
proj_kernel(const float* __restrict__ emb,
            const float* __restrict__ Wf, const float* __restrict__ bf,
            const float* __restrict__ Wb, const float* __restrict__ bb) {
    extern __shared__ uint4 xsh[];   // [128 v][16 uint4]  (64 half2 per v)
    int vt   = blockIdx.x * PROJ_VT;
    int d    = blockIdx.y >> 1;
    int half = blockIdx.y & 1;
    int j    = threadIdx.x;
    int r    = half * 256 + j;

    const float* W    = d ? Wb : Wf;
    const float* bias = d ? bb : bf;
    float* outp = g_proj[d];

    // stage x tile as half2: each thread converts 16 float4 -> 8 uint4
    {
        const float4* src = (const float4*)(emb + vt * En);
        uint2* dst = (uint2*)xsh;
        for (int i = j; i < PROJ_VT * En / 4; i += 256) {
            float4 e = src[i];
            __half2 lo = __floats2half2_rn(e.x, e.y);
            __half2 hi = __floats2half2_rn(e.z, e.w);
            dst[i] = make_uint2(*(unsigned*)&lo, *(unsigned*)&hi);
        }
    }

    // row weights: 128 floats -> 64 half2 regs
    __half2 wh[64];
    {
        const float4* pw = (const float4*)(W + r * En);
#pragma unroll
        for (int q = 0; q < 32; q++) {
            float4 v = pw[q];
            wh[2 * q]     = __floats2half2_rn(v.x, v.y);
            wh[2 * q + 1] = __floats2half2_rn(v.z, v.w);
        }
    }
    float bj = bias[r];
    __syncthreads();

    for (int v = 0; v < PROJ_VT; v += 2) {
        const uint4* xv0 = xsh + v * 16;
        const uint4* xv1 = xsh + (v + 1) * 16;
        __half2 a[8], b[8];
#pragma unroll
        for (int t = 0; t < 16; t++) {
            uint4 u0 = xv0[t];                       // broadcast LDS.128
            uint4 u1 = xv1[t];
            const __half2* x0 = (const __half2*)&u0;
            const __half2* x1 = (const __half2*)&u1;
#pragma unroll
            for (int i2 = 0; i2 < 4; i2++) {
                int n = t * 4 + i2;
                if (n < 8) {
                    a[n] = __hmul2(wh[n], x0[i2]);
                    b[n] = __hmul2(wh[n], x1[i2]);
                } else {
                    a[n & 7] = __hfma2(wh[n], x0[i2], a[n & 7]);
                    b[n & 7] = __hfma2(wh[n], x1[i2], b[n & 7]);
                }
            }
        }
        __half2 sa = __hadd2(__hadd2(__hadd2(a[0], a[1]), __hadd2(a[2], a[3])),
                             __hadd2(__hadd2(a[4], a[5]), __hadd2(a[6], a[7])));
        __half2 sb = __hadd2(__hadd2(__hadd2(b[0], b[1]), __hadd2(b[2], b[3])),
                             __hadd2(__hadd2(b[4], b[5]), __hadd2(b[6], b[7])));
        outp[(vt + v) * 512 + r]     = __low2float(sa) + __high2float(sa) + bj;
        outp[(vt + v + 1) * 512 + r] = __low2float(sb) + __high2float(sb) + bj;
    }
}

// ---------------------------------------------------------------------------
// Kernel B: recurrent biLSTM with fused ragged max-pool — fp16 HFMA2 dots.
// grid 128 = (sample, direction); 256 threads (best measured structure).
// Pair (2j, 2j+1): thread p owns h-columns [64p, 64p+64) of gate rows
// i_j, f_j, g_j, o_j. All 4 gate halves in registers as half2 (128 regs).
// Changes vs R14: (a) 4 half2 accumulators per gate (reduction 28 -> 12
// hadd2); (b) ONE shuffle round: all 4 fp32 partials exchanged concurrently
// (xg pre-added on the owning lane), then BOTH lanes compute all activations
// and the c/h update redundantly (fp32 add commutes -> pair stays identical).
// Removes the serial product-shfl and all lane selects from the tail.
// ---------------------------------------------------------------------------
__global__ void __launch_bounds__(256, 1)
lstm_kernel(const int* __restrict__ sentence, const int* __restrict__ lens,
            const float* __restrict__ Whhf, const float* __restrict__ Whhb) {
    __shared__ uint4 h2raw[2][18];        // 2 x 72 half2: [0..31], pad 4, [36..67]
    __shared__ float wmax[Sn * 128];      // [8][128]

    int bid = blockIdx.x;
    int b = bid >> 1, d = bid & 1;
    int L = lens[b];
    int w = (L + 7) >> 3;          // pooling window (>=128 for L in [1024,2048])
    int k = threadIdx.x;
    int j = k >> 1, p = k & 1;

    const float* W     = d ? Whhb : Whhf;
    const float* projd = g_proj[d];
    const int*   toks  = sentence + b * Tn;

    int rX = p ? (128 + j) : j;          // f : i   (xg row for gX)
    int rY = p ? (384 + j) : (256 + j);  // o : g   (xg row for gY)

    // --- load W_hh halves, quantize to half2 pairs (cols 2m, 2m+1) ---
    __half2 w2i[32], w2f[32], w2g[32], w2o[32];
    {
        int co = 64 * p;
        const float4* pi_ = (const float4*)(W + j * En + co);
        const float4* pf_ = (const float4*)(W + (128 + j) * En + co);
        const float4* pg_ = (const float4*)(W + (256 + j) * En + co);
        const float4* po_ = (const float4*)(W + (384 + j) * En + co);
#pragma unroll
        for (int q = 0; q < 16; q++) {
            float4 vi = pi_[q];
            w2i[2 * q]     = __floats2half2_rn(vi.x, vi.y);
            w2i[2 * q + 1] = __floats2half2_rn(vi.z, vi.w);
            float4 vf = pf_[q];
            w2f[2 * q]     = __floats2half2_rn(vf.x, vf.y);
            w2f[2 * q + 1] = __floats2half2_rn(vf.z, vf.w);
            float4 vg = pg_[q];
            w2g[2 * q]     = __floats2half2_rn(vg.x, vg.y);
            w2g[2 * q + 1] = __floats2half2_rn(vg.z, vg.w);
            float4 vo = po_[q];
            w2o[2 * q]     = __floats2half2_rn(vo.x, vo.y);
            w2o[2 * q + 1] = __floats2half2_rn(vo.z, vo.w);
        }
    }
    // zero both h buffers
    if (k < 36) {
        ((uint*)h2raw[0])[k * 2] = 0; ((uint*)h2raw[0])[k * 2 + 1] = 0;
        ((uint*)h2raw[1])[k * 2] = 0; ((uint*)h2raw[1])[k * 2 + 1] = 0;
    }
    __syncthreads();

    float c = 0.f;
    float rmax = -3.402823e38f;
    int sdir = d ? -1 : 1;
    int seg  = d ? 7 : 0;                  // (L-1)/w == 7 for all valid L
    int cnt  = d ? (L - 7 * w) : w;        // steps until current segment closes
    int idx  = d ? (L - 1) : 0;            // current time index
    // h2 writer: threads with (k&3)==1 own entry m = k>>2 (pairs h_2m, h_2m+1)
    int went  = (k >> 2) + (((k >> 2) >> 5) << 2);   // padded entry index
    bool isw  = (k & 3) == 1;

    int rbuf = 0;

    // deep prefetch: xg for step 0; token for step 1 already in flight
    int ni   = idx + sdir; ni = ni < 0 ? 0 : (ni >= L ? L - 1 : ni);
    int tok0 = toks[idx];
    int tokn = toks[ni];                       // token for t+1
    float xga = __ldg(projd + tok0 * 512 + rX);
    float xgb = __ldg(projd + tok0 * 512 + rY);

    for (int s = 0; s < L; s++) {
        // prefetch: tok(t+2) and proj[tok(t+1)] — each LDG gets a full step of cover
        int nni = ni + sdir; nni = nni < 0 ? 0 : (nni >= L ? L - 1 : nni);
        int toknn = __ldg(toks + nni);
        float nxa = __ldg(projd + tokn * 512 + rX);
        float nxb = __ldg(projd + tokn * 512 + rY);

        // --- load this thread's h half (32 half2) as 8 LDS.128 ---
        uint4 hu[8];
        {
            const uint4* hb = h2raw[rbuf] + p * 9;   // 36 half2 = 9 uint4 offset
#pragma unroll
            for (int i = 0; i < 8; i++) hu[i] = hb[i];
        }
        const __half2* hp = (const __half2*)hu;

        // --- 4 half-row dots, 4 half2 accumulator chains, init via mul ---
        __half2 ai[4], af[4], ag[4], ao[4];
#pragma unroll
        for (int m = 0; m < 4; m++) {
            __half2 h2 = hp[m];
            ai[m] = __hmul2(w2i[m], h2);
            af[m] = __hmul2(w2f[m], h2);
            ag[m] = __hmul2(w2g[m], h2);
            ao[m] = __hmul2(w2o[m], h2);
        }
#pragma unroll
        for (int m = 4; m < 32; m++) {
            int a = m & 3;
            __half2 h2 = hp[m];
            ai[a] = __hfma2(w2i[m], h2, ai[a]);
            af[a] = __hfma2(w2f[m], h2, af[a]);
            ag[a] = __hfma2(w2g[m], h2, ag[a]);
            ao[a] = __hfma2(w2o[m], h2, ao[a]);
        }
        // reduce (12 hadd2) then promote to fp32
        __half2 si = __hadd2(__hadd2(ai[0], ai[1]), __hadd2(ai[2], ai[3]));
        __half2 sf = __hadd2(__hadd2(af[0], af[1]), __hadd2(af[2], af[3]));
        __half2 sg = __hadd2(__hadd2(ag[0], ag[1]), __hadd2(ag[2], ag[3]));
        __half2 so = __hadd2(__hadd2(ao[0], ao[1]), __hadd2(ao[2], ao[3]));
        float pi = __low2float(si) + __high2float(si);
        float pf = __low2float(sf) + __high2float(sf);
        float pg = __low2float(sg) + __high2float(sg);
        float po = __low2float(so) + __high2float(so);

        // xg pre-add on the owning lane (even owns i,g rows; odd owns f,o rows)
        if (p) { pf += xga; po += xgb; }
        else   { pi += xga; pg += xgb; }

        // ONE shuffle round: 4 concurrent exchanges -> both lanes get all gates.
        // fp32 add commutes, so the pair computes bit-identical c/h.
        float gi = pi + __shfl_xor_sync(0xffffffffu, pi, 1);
        float gf = pf + __shfl_xor_sync(0xffffffffu, pf, 1);
        float gg = pg + __shfl_xor_sync(0xffffffffu, pg, 1);
        float go = po + __shfl_xor_sync(0xffffffffu, po, 1);

        // activations on MUFU tanh (all lanes, no selects)
        float vi = sigm_fast(gi);
        float vf = sigm_fast(gf);
        float tg = tanhf_fast(gg);
        float vo = sigm_fast(go);

        c = vf * c + vi * tg;
        float hn = vo * tanhf_fast(c);

        // pack h pair (h_2m, h_2m+1): writer k=4m+1 gets h_2m+1 via xor 2
        float hpart = __shfl_xor_sync(0xffffffffu, hn, 2);
        if (isw) {
            ((__half2*)h2raw[rbuf ^ 1])[went] = __floats2half2_rn(hn, hpart);
        }
        __syncthreads();
        if (p) rmax = fmaxf(rmax, hn);

        // segment boundary: flush register max (7-8 crossings per chain)
        if (--cnt == 0) {
            if (p) wmax[seg * 128 + j] = rmax;
            rmax = -3.402823e38f;
            seg += sdir;
            cnt = w;
        }
        idx = ni; ni = nni; tokn = toknn;
        xga = nxa; xgb = nxb;
        rbuf ^= 1;                                  // swap double buffers
    }
    if (cnt != w && p) wmax[seg * 128 + j] = rmax;   // pending partial segment
    __syncthreads();

    // epilogue: only window 7 can overlap the zero pad (pad length < 8 <= w)
    bool pad7 = (8 * w > L);
    for (int i = k; i < Sn * 128; i += 256) {
        int s = i >> 7, kk = i & 127;
        float v = wmax[i];
        if (s == 7 && pad7) v = fmaxf(v, 0.f);
        g_pooled[(b * Sn + s) * 256 + d * 128 + kk] = v;
    }
}

// ---------------------------------------------------------------------------
// Kernel C: out[b][c] = b_dense[c] + sum_{s,h} pooled[b][s][h] * W_dense[c][h*8+s]
// ---------------------------------------------------------------------------
__global__ void dense_kernel(const float* __restrict__ Wd, const float* __restrict__ bd,
                             float* __restrict__ out) {
    int b = blockIdx.x, t = threadIdx.x;
    const float* p = g_pooled + b * 2048;
    float a0 = 0.f, a1 = 0.f;
    for (int i = t; i < 2048; i += 256) {
        int s = i >> 8, hh = i & 255;
        float v = p[i];
        a0 += v * Wd[hh * 8 + s];
        a1 += v * Wd[2048 + hh * 8 + s];
    }
#pragma unroll
    for (int o = 16; o > 0; o >>= 1) {
        a0 += __shfl_down_sync(0xffffffffu, a0, o);
        a1 += __shfl_down_sync(0xffffffffu, a1, o);
    }
    __shared__ float r0[8], r1[8];
    if ((t & 31) == 0) { r0[t >> 5] = a0; r1[t >> 5] = a1; }
    __syncthreads();
    if (t == 0) {
        float o0 = bd[0], o1 = bd[1];
#pragma unroll
        for (int i = 0; i < 8; i++) { o0 += r0[i]; o1 += r1[i]; }
        out[b * 2]     = o0;
        out[b * 2 + 1] = o1;
    }
}

// ---------------------------------------------------------------------------
// launch
// ---------------------------------------------------------------------------
extern "C" void kernel_launch(void* const* d_in, const int* in_sizes, int n_in,
                              void* d_out, int out_size) {
    const int*   sentence = (const int*)d_in[0];
    const int*   lens     = (const int*)d_in[1];
    const float* emb      = (const float*)d_in[2];
    const float* Wihf     = (const float*)d_in[3];
    const float* Whhf     = (const float*)d_in[4];
    const float* bf       = (const float*)d_in[5];
    const float* Wihb     = (const float*)d_in[6];
    const float* Whhb     = (const float*)d_in[7];
    const float* bb       = (const float*)d_in[8];
    const float* Wd       = (const float*)d_in[9];
    const float* bd       = (const float*)d_in[10];
    float* out = (float*)d_out;

    cudaFuncSetAttribute(proj_kernel, cudaFuncAttributeMaxDynamicSharedMemorySize, PROJ_SMEM);

    proj_kernel<<<dim3(Vn / PROJ_VT, 4), 256, PROJ_SMEM>>>(emb, Wihf, bf, Wihb, bb);
    lstm_kernel<<<128, 256>>>(sentence, lens, Whhf, Whhb);
    dense_kernel<<<Bn, 256>>>(Wd, bd, out);
}

// round 17
// speedup vs baseline: 1.3487x; 1.0607x over previous
#include <cuda_runtime.h>
#include <cuda_fp16.h>
#include <cstdint>

// Problem constants
#define Tn   2048
#define Bn   64
#define Vn   4096
#define En   128
#define H2n  128
#define Sn   8

// Scratch (no allocations allowed)
__device__ float g_proj[2][Vn * 512];      // proj[d][v][gate] = W_ih_d @ emb[v] + b_d (16 MB, L2-resident)
__device__ float g_pooled[Bn * Sn * 256];  // pooled[b][s][h]  (512 KB)

// ---------------------------------------------------------------------------
// helpers
// ---------------------------------------------------------------------------
__device__ __forceinline__ float tanhf_fast(float x) {
    float y; asm("tanh.approx.f32 %0, %1;" : "=f"(y) : "f"(x)); return y;
}
// sigmoid via MUFU tanh: sig(x) = 0.5*tanh(0.5x) + 0.5
__device__ __forceinline__ float sigm_fast(float x) {
    return fmaf(0.5f, tanhf_fast(0.5f * x), 0.5f);
}
// fp16 horizontal sum of a half2 -> float (PRMT on alu pipe + 1 hadd2 + 1 cvt)
__device__ __forceinline__ float hsum2(__half2 v) {
    return __low2float(__hadd2(v, __lowhigh2highlow(v)));
}

// ---------------------------------------------------------------------------
// Kernel A: proj[d][v][r] = dot(emb[v], W_ih_d[r]) + b_d[r]   (fp16 dots)
// grid (32, 4): y -> (dir, row-half). 256 threads; thread j owns row r.
// x tile staged as half2 in smem; row weights as 64 half2 regs. 128 v per
// block, 2 v per iter (ILP). Output fp32.
// ---------------------------------------------------------------------------
#define PROJ_VT 128
#define PROJ_SMEM (PROJ_VT * En * 2)   // 32768 B (half2 x tile)

__global__ void __launch_bounds__(256, 1)
proj_kernel(const float* __restrict__ emb,
            const float* __restrict__ Wf, const float* __restrict__ bf,
            const float* __restrict__ Wb, const float* __restrict__ bb) {
    extern __shared__ uint4 xsh[];   // [128 v][16 uint4]  (64 half2 per v)
    int vt   = blockIdx.x * PROJ_VT;
    int d    = blockIdx.y >> 1;
    int half = blockIdx.y & 1;
    int j    = threadIdx.x;
    int r    = half * 256 + j;

    const float* W    = d ? Wb : Wf;
    const float* bias = d ? bb : bf;
    float* outp = g_proj[d];

    // stage x tile as half2: each thread converts 16 float4 -> 8 uint4
    {
        const float4* src = (const float4*)(emb + vt * En);
        uint2* dst = (uint2*)xsh;
        for (int i = j; i < PROJ_VT * En / 4; i += 256) {
            float4 e = src[i];
            __half2 lo = __floats2half2_rn(e.x, e.y);
            __half2 hi = __floats2half2_rn(e.z, e.w);
            dst[i] = make_uint2(*(unsigned*)&lo, *(unsigned*)&hi);
        }
    }

    // row weights: 128 floats -> 64 half2 regs
    __half2 wh[64];
    {
        const float4* pw = (const float4*)(W + r * En);
#pragma unroll
        for (int q = 0; q < 32; q++) {
            float4 v = pw[q];
            wh[2 * q]     = __floats2half2_rn(v.x, v.y);
            wh[2 * q + 1] = __floats2half2_rn(v.z, v.w);
        }
    }
    float bj = bias[r];
    __syncthreads();

    for (int v = 0; v < PROJ_VT; v += 2) {
        const uint4* xv0 = xsh + v * 16;
        const uint4* xv1 = xsh + (v + 1) * 16;
        __half2 a[8], b[8];
#pragma unroll
        for (int t = 0; t < 16; t++) {
            uint4 u0 = xv0[t];                       // broadcast LDS.128
            uint4 u1 = xv1[t];
            const __half2* x0 = (const __half2*)&u0;
            const __half2* x1 = (const __half2*)&u1;
#pragma unroll
            for (int i2 = 0; i2 < 4; i2++) {
                int n = t * 4 + i2;
                if (n < 8) {
                    a[n] = __hmul2(wh[n], x0[i2]);
                    b[n] = __hmul2(wh[n], x1[i2]);
                } else {
                    a[n & 7] = __hfma2(wh[n], x0[i2], a[n & 7]);
                    b[n & 7] = __hfma2(wh[n], x1[i2], b[n & 7]);
                }
            }
        }
        __half2 sa = __hadd2(__hadd2(__hadd2(a[0], a[1]), __hadd2(a[2], a[3])),
                             __hadd2(__hadd2(a[4], a[5]), __hadd2(a[6], a[7])));
        __half2 sb = __hadd2(__hadd2(__hadd2(b[0], b[1]), __hadd2(b[2], b[3])),
                             __hadd2(__hadd2(b[4], b[5]), __hadd2(b[6], b[7])));
        outp[(vt + v) * 512 + r]     = __low2float(sa) + __high2float(sa) + bj;
        outp[(vt + v + 1) * 512 + r] = __low2float(sb) + __high2float(sb) + bj;
    }
}

// ---------------------------------------------------------------------------
// Kernel B: recurrent biLSTM with fused ragged max-pool — fp16 HFMA2 dots.
// grid 128 = (sample, direction); 256 threads (best measured structure).
// Pair (2j, 2j+1): thread p owns h-columns [64p, 64p+64) of gate rows
// i_j, f_j, g_j, o_j. All 4 gate halves in registers as half2 (128 regs).
// Changes vs R15: (a) 2 half2 accumulators per gate + fp16 horizontal sum
// (PRMT/alu + 1 hadd2 + 1 cvt per gate) — ~32 fewer fma-pipe cyc/step;
// (b) direct STS.16 h store per odd lane — removes the pack shuffle from
// the pre-barrier critical path. Single shfl round for gate partials; both
// lanes compute the c/h update redundantly (fp32 add commutes).
// ---------------------------------------------------------------------------
__global__ void __launch_bounds__(256, 1)
lstm_kernel(const int* __restrict__ sentence, const int* __restrict__ lens,
            const float* __restrict__ Whhf, const float* __restrict__ Whhb) {
    __shared__ uint4 h2raw[2][18];        // 2 x 144 halves: h[0..63], pad 8, h[64..127]
    __shared__ float wmax[Sn * 128];      // [8][128]

    int bid = blockIdx.x;
    int b = bid >> 1, d = bid & 1;
    int L = lens[b];
    int w = (L + 7) >> 3;          // pooling window (>=128 for L in [1024,2048])
    int k = threadIdx.x;
    int j = k >> 1, p = k & 1;

    const float* W     = d ? Whhb : Whhf;
    const float* projd = g_proj[d];
    const int*   toks  = sentence + b * Tn;

    int rX = p ? (128 + j) : j;          // f : i   (xg row for gX)
    int rY = p ? (384 + j) : (256 + j);  // o : g   (xg row for gY)

    // --- load W_hh halves, quantize to half2 pairs (cols 2m, 2m+1) ---
    __half2 w2i[32], w2f[32], w2g[32], w2o[32];
    {
        int co = 64 * p;
        const float4* pi_ = (const float4*)(W + j * En + co);
        const float4* pf_ = (const float4*)(W + (128 + j) * En + co);
        const float4* pg_ = (const float4*)(W + (256 + j) * En + co);
        const float4* po_ = (const float4*)(W + (384 + j) * En + co);
#pragma unroll
        for (int q = 0; q < 16; q++) {
            float4 vi = pi_[q];
            w2i[2 * q]     = __floats2half2_rn(vi.x, vi.y);
            w2i[2 * q + 1] = __floats2half2_rn(vi.z, vi.w);
            float4 vf = pf_[q];
            w2f[2 * q]     = __floats2half2_rn(vf.x, vf.y);
            w2f[2 * q + 1] = __floats2half2_rn(vf.z, vf.w);
            float4 vg = pg_[q];
            w2g[2 * q]     = __floats2half2_rn(vg.x, vg.y);
            w2g[2 * q + 1] = __floats2half2_rn(vg.z, vg.w);
            float4 vo = po_[q];
            w2o[2 * q]     = __floats2half2_rn(vo.x, vo.y);
            w2o[2 * q + 1] = __floats2half2_rn(vo.z, vo.w);
        }
    }
    // zero both h buffers (36 uint4 total)
    if (k < 36) {
        ((uint*)h2raw[0])[k * 2] = 0; ((uint*)h2raw[0])[k * 2 + 1] = 0;
        ((uint*)h2raw[1])[k * 2] = 0; ((uint*)h2raw[1])[k * 2 + 1] = 0;
    }
    __syncthreads();

    float c = 0.f;
    float rmax = -3.402823e38f;
    int sdir = d ? -1 : 1;
    int seg  = d ? 7 : 0;                  // (L-1)/w == 7 for all valid L
    int cnt  = d ? (L - 7 * w) : w;        // steps until current segment closes
    int idx  = d ? (L - 1) : 0;            // current time index
    int hoff = j + ((j >> 6) << 3);        // padded half-index of h_j (pad 8 halves)

    int rbuf = 0;

    // deep prefetch: xg for step 0; token for step 1 already in flight
    int ni   = idx + sdir; ni = ni < 0 ? 0 : (ni >= L ? L - 1 : ni);
    int tok0 = toks[idx];
    int tokn = toks[ni];                       // token for t+1
    float xga = __ldg(projd + tok0 * 512 + rX);
    float xgb = __ldg(projd + tok0 * 512 + rY);

    for (int s = 0; s < L; s++) {
        // prefetch: tok(t+2) and proj[tok(t+1)] — each LDG gets a full step of cover
        int nni = ni + sdir; nni = nni < 0 ? 0 : (nni >= L ? L - 1 : nni);
        int toknn = __ldg(toks + nni);
        float nxa = __ldg(projd + tokn * 512 + rX);
        float nxb = __ldg(projd + tokn * 512 + rY);

        // --- load this thread's h half (32 half2) as 8 LDS.128 ---
        uint4 hu[8];
        {
            const uint4* hb = h2raw[rbuf] + p * 9;   // 72 halves = 9 uint4 offset
#pragma unroll
            for (int i = 0; i < 8; i++) hu[i] = hb[i];
        }
        const __half2* hp = (const __half2*)hu;

        // --- 4 half-row dots, 2 half2 accumulator chains each, init via mul ---
        __half2 ai0, ai1, af0, af1, ag0, ag1, ao0, ao1;
        {
            __half2 h0 = hp[0], h1 = hp[1];
            ai0 = __hmul2(w2i[0], h0); ai1 = __hmul2(w2i[1], h1);
            af0 = __hmul2(w2f[0], h0); af1 = __hmul2(w2f[1], h1);
            ag0 = __hmul2(w2g[0], h0); ag1 = __hmul2(w2g[1], h1);
            ao0 = __hmul2(w2o[0], h0); ao1 = __hmul2(w2o[1], h1);
        }
#pragma unroll
        for (int m = 2; m < 32; m += 2) {
            __half2 h0 = hp[m], h1 = hp[m + 1];
            ai0 = __hfma2(w2i[m], h0, ai0); ai1 = __hfma2(w2i[m + 1], h1, ai1);
            af0 = __hfma2(w2f[m], h0, af0); af1 = __hfma2(w2f[m + 1], h1, af1);
            ag0 = __hfma2(w2g[m], h0, ag0); ag1 = __hfma2(w2g[m + 1], h1, ag1);
            ao0 = __hfma2(w2o[m], h0, ao0); ao1 = __hfma2(w2o[m + 1], h1, ao1);
        }
        // reduce: 1 hadd2 + fp16 horizontal sum per gate
        float pi = hsum2(__hadd2(ai0, ai1));
        float pf = hsum2(__hadd2(af0, af1));
        float pg = hsum2(__hadd2(ag0, ag1));
        float po = hsum2(__hadd2(ao0, ao1));

        // xg pre-add on the owning lane (even owns i,g rows; odd owns f,o rows)
        if (p) { pf += xga; po += xgb; }
        else   { pi += xga; pg += xgb; }

        // ONE shuffle round: 4 concurrent exchanges -> both lanes get all gates.
        // fp32 add commutes, so the pair computes bit-identical c/h.
        float gi = pi + __shfl_xor_sync(0xffffffffu, pi, 1);
        float gf = pf + __shfl_xor_sync(0xffffffffu, pf, 1);
        float gg = pg + __shfl_xor_sync(0xffffffffu, pg, 1);
        float go = po + __shfl_xor_sync(0xffffffffu, po, 1);

        // activations on MUFU tanh (all lanes, no selects)
        float vi = sigm_fast(gi);
        float vf = sigm_fast(gf);
        float tg = tanhf_fast(gg);
        float vo = sigm_fast(go);

        c = vf * c + vi * tg;
        float hn = vo * tanhf_fast(c);

        // direct STS.16: each odd lane stores its own h_j (no pack shuffle)
        if (p) ((__half*)h2raw)[(rbuf ^ 1) * 144 + hoff] = __float2half_rn(hn);
        __syncthreads();
        if (p) rmax = fmaxf(rmax, hn);

        // segment boundary: flush register max (7-8 crossings per chain)
        if (--cnt == 0) {
            if (p) wmax[seg * 128 + j] = rmax;
            rmax = -3.402823e38f;
            seg += sdir;
            cnt = w;
        }
        idx = ni; ni = nni; tokn = toknn;
        xga = nxa; xgb = nxb;
        rbuf ^= 1;                                  // swap double buffers
    }
    if (cnt != w && p) wmax[seg * 128 + j] = rmax;   // pending partial segment
    __syncthreads();

    // epilogue: only window 7 can overlap the zero pad (pad length < 8 <= w)
    bool pad7 = (8 * w > L);
    for (int i = k; i < Sn * 128; i += 256) {
        int s = i >> 7, kk = i & 127;
        float v = wmax[i];
        if (s == 7 && pad7) v = fmaxf(v, 0.f);
        g_pooled[(b * Sn + s) * 256 + d * 128 + kk] = v;
    }
}

// ---------------------------------------------------------------------------
// Kernel C: out[b][c] = b_dense[c] + sum_{s,h} pooled[b][s][h] * W_dense[c][h*8+s]
// ---------------------------------------------------------------------------
__global__ void dense_kernel(const float* __restrict__ Wd, const float* __restrict__ bd,
                             float* __restrict__ out) {
    int b = blockIdx.x, t = threadIdx.x;
    const float* p = g_pooled + b * 2048;
    float a0 = 0.f, a1 = 0.f;
    for (int i = t; i < 2048; i += 256) {
        int s = i >> 8, hh = i & 255;
        float v = p[i];
        a0 += v * Wd[hh * 8 + s];
        a1 += v * Wd[2048 + hh * 8 + s];
    }
#pragma unroll
    for (int o = 16; o > 0; o >>= 1) {
        a0 += __shfl_down_sync(0xffffffffu, a0, o);
        a1 += __shfl_down_sync(0xffffffffu, a1, o);
    }
    __shared__ float r0[8], r1[8];
    if ((t & 31) == 0) { r0[t >> 5] = a0; r1[t >> 5] = a1; }
    __syncthreads();
    if (t == 0) {
        float o0 = bd[0], o1 = bd[1];
#pragma unroll
        for (int i = 0; i < 8; i++) { o0 += r0[i]; o1 += r1[i]; }
        out[b * 2]     = o0;
        out[b * 2 + 1] = o1;
    }
}

// ---------------------------------------------------------------------------
// launch
// ---------------------------------------------------------------------------
extern "C" void kernel_launch(void* const* d_in, const int* in_sizes, int n_in,
                              void* d_out, int out_size) {
    const int*   sentence = (const int*)d_in[0];
    const int*   lens     = (const int*)d_in[1];
    const float* emb      = (const float*)d_in[2];
    const float* Wihf     = (const float*)d_in[3];
    const float* Whhf     = (const float*)d_in[4];
    const float* bf       = (const float*)d_in[5];
    const float* Wihb     = (const float*)d_in[6];
    const float* Whhb     = (const float*)d_in[7];
    const float* bb       = (const float*)d_in[8];
    const float* Wd       = (const float*)d_in[9];
    const float* bd       = (const float*)d_in[10];
    float* out = (float*)d_out;

    cudaFuncSetAttribute(proj_kernel, cudaFuncAttributeMaxDynamicSharedMemorySize, PROJ_SMEM);

    proj_kernel<<<dim3(Vn / PROJ_VT, 4), 256, PROJ_SMEM>>>(emb, Wihf, bf, Wihb, bb);
    lstm_kernel<<<128, 256>>>(sentence, lens, Whhf, Whhb);
    dense_kernel<<<Bn, 256>>>(Wd, bd, out);
}